// round 1
// baseline (speedup 1.0000x reference)
#include <cuda_runtime.h>
#include <math.h>
#include <stdint.h>

#define SEQ    2048
#define BATCH  2
#define HIDDEN 2048
#define NKV    4
#define NH     16
#define HD     128
#define QPG    4
#define GS     768            // (QPG+2)*HD
#define TP     3072           // NKV*GS
#define M_TOT  (SEQ*BATCH)    // 4096
#define EMB    2048           // NH*HD

// ---- scratch (device globals: no allocation allowed) ----
__device__ float g_qkv[M_TOT * TP];            // 48 MB  qkv projection
__device__ float g_qt [BATCH * NH  * HD * SEQ]; // 32 MB  Q, d-major, pre-scaled
__device__ float g_kt [BATCH * NKV * HD * SEQ]; //  8 MB  K, d-major
__device__ float g_o  [M_TOT * EMB];            // 32 MB  attention output

// ============================================================
// GEMM: C[M][N] = A[M][K] * B[N][K]^T   (both operands K-major)
// 128x128 block tile, BK=16, 256 threads, 8x8 per-thread tile
// ============================================================
__global__ __launch_bounds__(256, 2)
void sgemm_nt(const float* __restrict__ A, const float* __restrict__ B,
              float* __restrict__ C, int M, int N, int K) {
    __shared__ float As[16][132];
    __shared__ float Bs[16][132];

    const int tid = threadIdx.x;
    const int ty  = tid >> 4;      // 0..15
    const int tx  = tid & 15;      // 0..15
    const int m0  = blockIdx.y << 7;
    const int n0  = blockIdx.x << 7;
    const int lr  = tid >> 2;      // 0..63
    const int lq  = tid & 3;       // k-quad

    const float* Ap = A + (size_t)(m0 + lr) * K + (lq << 2);
    const float* Bp = B + (size_t)(n0 + lr) * K + (lq << 2);

    float4 pa0 = *(const float4*)Ap;
    float4 pa1 = *(const float4*)(Ap + (size_t)64 * K);
    float4 pb0 = *(const float4*)Bp;
    float4 pb1 = *(const float4*)(Bp + (size_t)64 * K);

    float acc[8][8];
#pragma unroll
    for (int i = 0; i < 8; ++i)
#pragma unroll
        for (int j = 0; j < 8; ++j) acc[i][j] = 0.f;

    for (int k0 = 0; k0 < K; k0 += 16) {
        const int kq = lq << 2;
        As[kq+0][lr]    = pa0.x; As[kq+1][lr]    = pa0.y;
        As[kq+2][lr]    = pa0.z; As[kq+3][lr]    = pa0.w;
        As[kq+0][lr+64] = pa1.x; As[kq+1][lr+64] = pa1.y;
        As[kq+2][lr+64] = pa1.z; As[kq+3][lr+64] = pa1.w;
        Bs[kq+0][lr]    = pb0.x; Bs[kq+1][lr]    = pb0.y;
        Bs[kq+2][lr]    = pb0.z; Bs[kq+3][lr]    = pb0.w;
        Bs[kq+0][lr+64] = pb1.x; Bs[kq+1][lr+64] = pb1.y;
        Bs[kq+2][lr+64] = pb1.z; Bs[kq+3][lr+64] = pb1.w;
        __syncthreads();

        if (k0 + 16 < K) {
            Ap += 16; Bp += 16;
            pa0 = *(const float4*)Ap;
            pa1 = *(const float4*)(Ap + (size_t)64 * K);
            pb0 = *(const float4*)Bp;
            pb1 = *(const float4*)(Bp + (size_t)64 * K);
        }

#pragma unroll
        for (int kk = 0; kk < 16; ++kk) {
            float4 a0 = *(const float4*)&As[kk][ty << 2];
            float4 a1 = *(const float4*)&As[kk][64 + (ty << 2)];
            float4 b0 = *(const float4*)&Bs[kk][tx << 2];
            float4 b1 = *(const float4*)&Bs[kk][64 + (tx << 2)];
            float av[8] = {a0.x,a0.y,a0.z,a0.w,a1.x,a1.y,a1.z,a1.w};
            float bv[8] = {b0.x,b0.y,b0.z,b0.w,b1.x,b1.y,b1.z,b1.w};
#pragma unroll
            for (int i = 0; i < 8; ++i)
#pragma unroll
                for (int j = 0; j < 8; ++j)
                    acc[i][j] += av[i] * bv[j];
        }
        __syncthreads();
    }

#pragma unroll
    for (int i = 0; i < 8; ++i) {
        int r = m0 + ((i < 4) ? ((ty << 2) + i) : (64 + (ty << 2) + i - 4));
        float4 c0 = make_float4(acc[i][0], acc[i][1], acc[i][2], acc[i][3]);
        float4 c1 = make_float4(acc[i][4], acc[i][5], acc[i][6], acc[i][7]);
        *(float4*)&C[(size_t)r * N + n0 + (tx << 2)]      = c0;
        *(float4*)&C[(size_t)r * N + n0 + 64 + (tx << 2)] = c1;
    }
}

// ============================================================
// Transpose Q,K slices of qkv into d-major layout.
// Q gets pre-scaled by 1/sqrt(HD). vh 0..15 = Q heads, 16..19 = K heads.
// ============================================================
__global__ void transpose_qk(const float* __restrict__ qkv,
                             float* __restrict__ qt, float* __restrict__ kt) {
    __shared__ float tile[32][33];
    const int tid = threadIdx.x;
    const int tx  = tid & 31;
    const int ty  = tid >> 5;   // 0..7
    const int z   = blockIdx.z;
    const int b   = z / 20;
    const int vh  = z % 20;
    const int s0  = blockIdx.x << 5;
    const int d0  = blockIdx.y << 5;
    const bool isq = (vh < 16);
    const int col = isq ? ((vh >> 2) * GS + (vh & 3) * HD + d0)
                        : ((vh - 16) * GS + QPG * HD + d0);
#pragma unroll
    for (int i = 0; i < 32; i += 8) {
        int s = s0 + ty + i;
        tile[ty + i][tx] = qkv[(size_t)(s * BATCH + b) * TP + col + tx];
    }
    __syncthreads();
    float* out = isq ? (qt + (size_t)((b * NH + vh) * HD + d0) * SEQ)
                     : (kt + (size_t)((b * NKV + (vh - 16)) * HD + d0) * SEQ);
    const float scale = isq ? 0.08838834764831845f : 1.0f;  // 1/sqrt(128)
#pragma unroll
    for (int i = 0; i < 32; i += 8) {
        int d = ty + i;
        out[(size_t)d * SEQ + s0 + tx] = tile[tx][d] * scale;
    }
}

// ============================================================
// Flash attention: one CTA per (b, h, 64-query tile). KV tile = 64.
// Q,K read d-major (conflict-free float4 smem ops). V read from qkv.
// ============================================================
#define QS_LD 68
#define VS_LD 132
#define SS_LD 68
#define ATT_SMEM ((128*QS_LD*2 + 64*VS_LD + 64*SS_LD + 192) * 4)

__global__ __launch_bounds__(256, 1)
void attn_kernel(const float* __restrict__ qt, const float* __restrict__ kt,
                 const float* __restrict__ qkv, float* __restrict__ o) {
    extern __shared__ float sm[];
    float* Qs   = sm;                    // [128][68] d-major
    float* Ks   = Qs + 128 * QS_LD;      // [128][68] d-major
    float* Vs   = Ks + 128 * QS_LD;      // [64][132] s-major
    float* Ss   = Vs + 64 * VS_LD;       // [64][68]
    float* rowm = Ss + 64 * SS_LD;       // [64]
    float* rowl = rowm + 64;             // [64]
    float* rowa = rowl + 64;             // [64]

    const int tid = threadIdx.x;
    const int ty  = tid >> 4;  // 0..15 -> rows 4*ty+i
    const int tx  = tid & 15;  // 0..15 -> cols 4*tx+j / 64+4*tx+j
    const int b   = blockIdx.z;
    const int h   = blockIdx.y;
    const int s0  = blockIdx.x << 6;
    const int kvh = h >> 2;

    // load Q tile: [128 d][64 s]
    const float* qb = qt + (size_t)((b * NH + h) * HD) * SEQ + s0;
#pragma unroll
    for (int it = 0; it < 8; ++it) {
        int idx = tid + it * 256;      // 0..2047
        int d = idx >> 4, c = (idx & 15) << 2;
        *(float4*)&Qs[d * QS_LD + c] = *(const float4*)(qb + (size_t)d * SEQ + c);
    }
    if (tid < 64) { rowm[tid] = -1e30f; rowl[tid] = 0.f; }

    float oacc[4][8];
#pragma unroll
    for (int i = 0; i < 4; ++i)
#pragma unroll
        for (int j = 0; j < 8; ++j) oacc[i][j] = 0.f;

    const float* kb = kt + (size_t)((b * NKV + kvh) * HD) * SEQ;
    const float* vb = qkv + (size_t)b * TP + kvh * GS + (QPG + 1) * HD;

    for (int t0 = 0; t0 < SEQ; t0 += 64) {
        __syncthreads();   // previous iter done with Ks/Vs/Ss
        // load K tile: [128 d][64 s]
#pragma unroll
        for (int it = 0; it < 8; ++it) {
            int idx = tid + it * 256;
            int d = idx >> 4, c = (idx & 15) << 2;
            *(float4*)&Ks[d * QS_LD + c] =
                *(const float4*)(kb + (size_t)d * SEQ + t0 + c);
        }
        // load V tile: [64 s][128 d]
#pragma unroll
        for (int it = 0; it < 8; ++it) {
            int idx = tid + it * 256;
            int r = idx >> 5, c = (idx & 31) << 2;
            *(float4*)&Vs[r * VS_LD + c] =
                *(const float4*)(vb + (size_t)(t0 + r) * (BATCH * TP) + c);
        }
        __syncthreads();

        // S tile: rows 4ty+i, cols 4tx+j (pre-scaled Q)
        float sacc[4][4];
#pragma unroll
        for (int i = 0; i < 4; ++i)
#pragma unroll
            for (int j = 0; j < 4; ++j) sacc[i][j] = 0.f;
#pragma unroll 16
        for (int d = 0; d < 128; ++d) {
            float4 q4 = *(const float4*)&Qs[d * QS_LD + (ty << 2)];
            float4 k4 = *(const float4*)&Ks[d * QS_LD + (tx << 2)];
            float qa[4] = {q4.x, q4.y, q4.z, q4.w};
            float ka[4] = {k4.x, k4.y, k4.z, k4.w};
#pragma unroll
            for (int i = 0; i < 4; ++i)
#pragma unroll
                for (int j = 0; j < 4; ++j)
                    sacc[i][j] += qa[i] * ka[j];
        }
#pragma unroll
        for (int i = 0; i < 4; ++i)
#pragma unroll
            for (int j = 0; j < 4; ++j)
                Ss[((ty << 2) + i) * SS_LD + (tx << 2) + j] = sacc[i][j];
        __syncthreads();

        // online softmax: 4 threads per row, 16 cols each
        {
            const int row  = tid >> 2;
            const int part = (tid & 3) << 4;
            float* srow = &Ss[row * SS_LD + part];
            float mloc = srow[0];
#pragma unroll
            for (int c = 1; c < 16; ++c) mloc = fmaxf(mloc, srow[c]);
            mloc = fmaxf(mloc, __shfl_xor_sync(0xffffffffu, mloc, 1));
            mloc = fmaxf(mloc, __shfl_xor_sync(0xffffffffu, mloc, 2));
            float mold = rowm[row];
            float mnew = fmaxf(mold, mloc);
            float sl = 0.f;
#pragma unroll
            for (int c = 0; c < 16; ++c) {
                float p = __expf(srow[c] - mnew);
                srow[c] = p;
                sl += p;
            }
            sl += __shfl_xor_sync(0xffffffffu, sl, 1);
            sl += __shfl_xor_sync(0xffffffffu, sl, 2);
            if ((tid & 3) == 0) {
                float al = __expf(mold - mnew);
                rowa[row] = al;
                rowl[row] = rowl[row] * al + sl;
                rowm[row] = mnew;
            }
        }
        __syncthreads();

        // O accumulation with rescale
        float al[4];
#pragma unroll
        for (int i = 0; i < 4; ++i) al[i] = rowa[(ty << 2) + i];
#pragma unroll
        for (int i = 0; i < 4; ++i)
#pragma unroll
            for (int j = 0; j < 8; ++j) oacc[i][j] *= al[i];

#pragma unroll 8
        for (int kv = 0; kv < 64; ++kv) {
            float4 va = *(const float4*)&Vs[kv * VS_LD + (tx << 2)];
            float4 vc = *(const float4*)&Vs[kv * VS_LD + 64 + (tx << 2)];
            float p[4];
#pragma unroll
            for (int i = 0; i < 4; ++i)
                p[i] = Ss[((ty << 2) + i) * SS_LD + kv];
#pragma unroll
            for (int i = 0; i < 4; ++i) {
                oacc[i][0] += p[i] * va.x;
                oacc[i][1] += p[i] * va.y;
                oacc[i][2] += p[i] * va.z;
                oacc[i][3] += p[i] * va.w;
                oacc[i][4] += p[i] * vc.x;
                oacc[i][5] += p[i] * vc.y;
                oacc[i][6] += p[i] * vc.z;
                oacc[i][7] += p[i] * vc.w;
            }
        }
    }

    // epilogue: normalize and write O[(s*B+b)][h*HD + col]
#pragma unroll
    for (int i = 0; i < 4; ++i) {
        float inv = 1.0f / rowl[(ty << 2) + i];
        int m = (s0 + (ty << 2) + i) * BATCH + b;
        float4 w0 = make_float4(oacc[i][0]*inv, oacc[i][1]*inv,
                                oacc[i][2]*inv, oacc[i][3]*inv);
        float4 w1 = make_float4(oacc[i][4]*inv, oacc[i][5]*inv,
                                oacc[i][6]*inv, oacc[i][7]*inv);
        *(float4*)&o[(size_t)m * EMB + h * HD + (tx << 2)]      = w0;
        *(float4*)&o[(size_t)m * EMB + h * HD + 64 + (tx << 2)] = w1;
    }
}

// ============================================================
extern "C" void kernel_launch(void* const* d_in, const int* in_sizes, int n_in,
                              void* d_out, int out_size) {
    (void)in_sizes; (void)n_in; (void)out_size;
    const float* x      = (const float*)d_in[0];
    const float* w_qkv  = (const float*)d_in[1];
    const float* w_proj = (const float*)d_in[2];
    float* out = (float*)d_out;

    float *qkv, *qt, *kt, *o;
    cudaGetSymbolAddress((void**)&qkv, g_qkv);
    cudaGetSymbolAddress((void**)&qt,  g_qt);
    cudaGetSymbolAddress((void**)&kt,  g_kt);
    cudaGetSymbolAddress((void**)&o,   g_o);

    cudaFuncSetAttribute(attn_kernel,
                         cudaFuncAttributeMaxDynamicSharedMemorySize, ATT_SMEM);

    // 1) QKV projection: [4096,3072] = x[4096,2048] @ w_qkv[3072,2048]^T
    sgemm_nt<<<dim3(TP / 128, M_TOT / 128), 256>>>(x, w_qkv, qkv, M_TOT, TP, HIDDEN);

    // 2) Q/K transpose to d-major (Q pre-scaled)
    transpose_qk<<<dim3(SEQ / 32, HD / 32, BATCH * 20), 256>>>(qkv, qt, kt);

    // 3) flash attention
    attn_kernel<<<dim3(SEQ / 64, NH, BATCH), 256, ATT_SMEM>>>(qt, kt, qkv, o);

    // 4) output projection: [4096,2048] = o[4096,2048] @ w_proj[2048,2048]^T
    sgemm_nt<<<dim3(HIDDEN / 128, M_TOT / 128), 256>>>(o, w_proj, out, M_TOT, EMB, HIDDEN);
}

// round 5
// speedup vs baseline: 1.3036x; 1.3036x over previous
#include <cuda_runtime.h>
#include <cuda_bf16.h>
#include <math.h>
#include <stdint.h>

#define SEQ    2048
#define BATCH  2
#define HIDDEN 2048
#define NKV    4
#define NH     16
#define HD     128
#define QPG    4
#define GS     768            // (QPG+2)*HD
#define TP     3072           // NKV*GS
#define M_TOT  (SEQ*BATCH)    // 4096
#define EMB    2048           // NH*HD

// ---- scratch (device globals: no allocation allowed) ----
__device__ float g_qkv[M_TOT * TP];             // 48 MB  qkv projection (fp32)
__device__ float g_qt [BATCH * NH  * HD * SEQ]; // 32 MB  Q, d-major, pre-scaled
__device__ float g_kt [BATCH * NKV * HD * SEQ]; //  8 MB  K, d-major
__device__ __nv_bfloat16 g_xh [M_TOT * HIDDEN];
__device__ __nv_bfloat16 g_xl [M_TOT * HIDDEN];
__device__ __nv_bfloat16 g_wqh[TP * HIDDEN];
__device__ __nv_bfloat16 g_wql[TP * HIDDEN];
__device__ __nv_bfloat16 g_wph[HIDDEN * EMB];
__device__ __nv_bfloat16 g_wpl[HIDDEN * EMB];
__device__ __nv_bfloat16 g_oh [M_TOT * EMB];
__device__ __nv_bfloat16 g_ol [M_TOT * EMB];

// ============================================================
// helpers
// ============================================================
__device__ __forceinline__ uint32_t smem_u32(const void* p) {
    uint32_t a;
    asm("{ .reg .u64 t; cvta.to.shared.u64 t, %1; cvt.u32.u64 %0, t; }"
        : "=r"(a) : "l"(p));
    return a;
}
__device__ __forceinline__ void cp_async16(uint32_t s, const void* g) {
    asm volatile("cp.async.cg.shared.global [%0], [%1], 16;" :: "r"(s), "l"(g));
}
__device__ __forceinline__ void ldm_x4(uint32_t addr, uint32_t* r) {
    asm volatile("ldmatrix.sync.aligned.m8n8.x4.shared.b16 {%0,%1,%2,%3}, [%4];"
                 : "=r"(r[0]), "=r"(r[1]), "=r"(r[2]), "=r"(r[3]) : "r"(addr));
}
__device__ __forceinline__ void mma16816(float* d, const uint32_t* a,
                                         const uint32_t* b) {
    asm volatile(
        "mma.sync.aligned.m16n8k16.row.col.f32.bf16.bf16.f32 "
        "{%0,%1,%2,%3}, {%4,%5,%6,%7}, {%8,%9}, {%0,%1,%2,%3};"
        : "+f"(d[0]), "+f"(d[1]), "+f"(d[2]), "+f"(d[3])
        : "r"(a[0]), "r"(a[1]), "r"(a[2]), "r"(a[3]), "r"(b[0]), "r"(b[1]));
}

// ============================================================
// hi/lo bf16 split (elementwise)
// ============================================================
__global__ void split_bf16(const float* __restrict__ src,
                           __nv_bfloat16* __restrict__ hi,
                           __nv_bfloat16* __restrict__ lo, int n4) {
    int i = blockIdx.x * blockDim.x + threadIdx.x;
    if (i >= n4) return;
    float4 v = ((const float4*)src)[i];
    float a[4] = {v.x, v.y, v.z, v.w};
    __nv_bfloat16 h[4], l[4];
#pragma unroll
    for (int j = 0; j < 4; ++j) {
        h[j] = __float2bfloat16_rn(a[j]);
        l[j] = __float2bfloat16_rn(a[j] - __bfloat162float(h[j]));
    }
    __nv_bfloat162 h01, h23, l01, l23;
    h01.x = h[0]; h01.y = h[1]; h23.x = h[2]; h23.y = h[3];
    l01.x = l[0]; l01.y = l[1]; l23.x = l[2]; l23.y = l[3];
    ((__nv_bfloat162*)hi)[2*i]   = h01;
    ((__nv_bfloat162*)hi)[2*i+1] = h23;
    ((__nv_bfloat162*)lo)[2*i]   = l01;
    ((__nv_bfloat162*)lo)[2*i+1] = l23;
}

// ============================================================
// bf16x3 GEMM via mma.sync: C[M][N](fp32) = A[M][K]*B[N][K]^T,
// C = Ah*Bh + Ah*Bl + Al*Bh.  128x128 CTA, BK=32, 4-stage cp.async.
// 8 warps (2 m x 4 n), warp tile 64x32, mma m16n8k16 bf16.
// smem tile pitch 80B (64B data + 16B skew -> conflict-free ldmatrix).
// ============================================================
#define GSTAGES 4
#define GBK 32
#define GPITCH 80                          // bytes per row
#define GTILE_B (128 * GPITCH)             // 10240
#define GSTAGE_B (4 * GTILE_B)             // Ah, Al, Bh, Bl = 40960
#define GEMM_SMEM (GSTAGES * GSTAGE_B)     // 163840

__device__ __forceinline__ void gemm_load_stage(
    uint32_t sb, int it, int tid,
    const __nv_bfloat16* Ah, const __nv_bfloat16* Al,
    const __nv_bfloat16* Bh, const __nv_bfloat16* Bl,
    int m0, int n0, int K) {
    const uint32_t st = sb + (it % GSTAGES) * GSTAGE_B;
    const int k0 = it * GBK;
    const __nv_bfloat16* srcs[4] = {Ah, Al, Bh, Bl};
    const int r0[4] = {m0, m0, n0, n0};
#pragma unroll
    for (int t = 0; t < 8; ++t) {
        int chunk = tid + t * 256;          // 0..2047
        int tbl = chunk >> 9;               // 512 chunks (16B) per tile
        int within = chunk & 511;
        int row = within >> 2, c = within & 3;
        uint32_t dst = st + tbl * GTILE_B + row * GPITCH + c * 16;
        cp_async16(dst, srcs[tbl] + (size_t)(r0[tbl] + row) * K + k0 + c * 8);
    }
    asm volatile("cp.async.commit_group;" ::: "memory");
}

__global__ __launch_bounds__(256, 1)
void gemm3x(const __nv_bfloat16* __restrict__ Ah, const __nv_bfloat16* __restrict__ Al,
            const __nv_bfloat16* __restrict__ Bh, const __nv_bfloat16* __restrict__ Bl,
            float* __restrict__ C, int N, int K) {
    extern __shared__ __align__(128) char smraw[];
    const uint32_t sb = smem_u32(smraw);
    const int tid  = threadIdx.x;
    const int lane = tid & 31;
    const int wid  = tid >> 5;
    const int wm   = wid & 1;              // 0..1
    const int wn   = wid >> 1;             // 0..3
    const int m0   = blockIdx.y << 7;
    const int n0   = blockIdx.x << 7;

    float acc[4][4][4];                    // [mi][nj][frag]
#pragma unroll
    for (int i = 0; i < 4; ++i)
#pragma unroll
        for (int j = 0; j < 4; ++j)
#pragma unroll
            for (int q = 0; q < 4; ++q) acc[i][j][q] = 0.f;

    const int T = K / GBK;
    for (int it = 0; it < GSTAGES - 1; ++it)
        gemm_load_stage(sb, it, tid, Ah, Al, Bh, Bl, m0, n0, K);

    // per-lane ldmatrix address components
    const uint32_t aRow = (wm << 6) + (lane & 15);         // within 128
    const uint32_t aCol = (lane >> 4) << 4;                // 0 / 16 bytes
    const uint32_t bRow = (wn << 5) + (((lane >> 4) & 1) << 3) + (lane & 7);
    const uint32_t bCol = ((lane >> 3) & 1) << 4;

    for (int ci = 0; ci < T; ++ci) {
        asm volatile("cp.async.wait_group %0;" :: "n"(GSTAGES - 2) : "memory");
        __syncthreads();
        const uint32_t st = sb + (ci % GSTAGES) * GSTAGE_B;

#pragma unroll
        for (int ac = 0; ac < 2; ++ac) {
            const uint32_t aBase = st + ac * GTILE_B;
#pragma unroll
            for (int k16 = 0; k16 < 2; ++k16) {
                uint32_t afr[4][4];
#pragma unroll
                for (int mi = 0; mi < 4; ++mi)
                    ldm_x4(aBase + (aRow + mi * 16) * GPITCH + k16 * 32 + aCol,
                           afr[mi]);
                const int nbc = (ac == 0) ? 2 : 1;    // Ah:{Bh,Bl}, Al:{Bh}
#pragma unroll
                for (int bc = 0; bc < 2; ++bc) {
                    if (bc >= nbc) break;
                    const uint32_t bBase = st + (2 + bc) * GTILE_B;
#pragma unroll
                    for (int p = 0; p < 2; ++p) {
                        uint32_t bfr[4];
                        ldm_x4(bBase + (bRow + p * 16) * GPITCH + k16 * 32 + bCol,
                               bfr);
#pragma unroll
                        for (int mi = 0; mi < 4; ++mi) {
                            mma16816(acc[mi][p * 2],     afr[mi], bfr);
                            mma16816(acc[mi][p * 2 + 1], afr[mi], bfr + 2);
                        }
                    }
                }
            }
        }
        __syncthreads();
        if (ci + GSTAGES - 1 < T)
            gemm_load_stage(sb, ci + GSTAGES - 1, tid, Ah, Al, Bh, Bl, m0, n0, K);
        else
            asm volatile("cp.async.commit_group;" ::: "memory");
    }

    // epilogue: thread (lane) holds rows lane>>2, +8; cols (lane&3)*2, +1
    const int rBase = m0 + (wm << 6) + (lane >> 2);
    const int cBase = n0 + (wn << 5) + ((lane & 3) << 1);
#pragma unroll
    for (int mi = 0; mi < 4; ++mi)
#pragma unroll
        for (int nj = 0; nj < 4; ++nj) {
            int r = rBase + mi * 16;
            int c = cBase + nj * 8;
            *(float2*)&C[(size_t)r * N + c] =
                make_float2(acc[mi][nj][0], acc[mi][nj][1]);
            *(float2*)&C[(size_t)(r + 8) * N + c] =
                make_float2(acc[mi][nj][2], acc[mi][nj][3]);
        }
}

// ============================================================
// Transpose Q,K slices of qkv into d-major layout (Q pre-scaled)
// ============================================================
__global__ void transpose_qk(const float* __restrict__ qkv,
                             float* __restrict__ qt, float* __restrict__ kt) {
    __shared__ float tile[32][33];
    const int tid = threadIdx.x;
    const int tx  = tid & 31;
    const int ty  = tid >> 5;
    const int z   = blockIdx.z;
    const int b   = z / 20;
    const int vh  = z % 20;
    const int s0  = blockIdx.x << 5;
    const int d0  = blockIdx.y << 5;
    const bool isq = (vh < 16);
    const int col = isq ? ((vh >> 2) * GS + (vh & 3) * HD + d0)
                        : ((vh - 16) * GS + QPG * HD + d0);
#pragma unroll
    for (int i = 0; i < 32; i += 8) {
        int s = s0 + ty + i;
        tile[ty + i][tx] = qkv[(size_t)(s * BATCH + b) * TP + col + tx];
    }
    __syncthreads();
    float* out = isq ? (qt + (size_t)((b * NH + vh) * HD + d0) * SEQ)
                     : (kt + (size_t)((b * NKV + (vh - 16)) * HD + d0) * SEQ);
    const float scale = isq ? 0.08838834764831845f : 1.0f;
#pragma unroll
    for (int i = 0; i < 32; i += 8) {
        int d = ty + i;
        out[(size_t)d * SEQ + s0 + tx] = tile[tx][d] * scale;
    }
}

// ============================================================
// Flash attention (fp32 SIMT). Epilogue emits hi/lo bf16 split.
// ============================================================
#define QS_LD 68
#define VS_LD 132
#define SS_LD 68
#define ATT_SMEM ((128*QS_LD*2 + 64*VS_LD + 64*SS_LD + 192) * 4)

__device__ __forceinline__ void split_store4(__nv_bfloat16* hp, __nv_bfloat16* lp,
                                             const float* v) {
    __nv_bfloat16 h[4], l[4];
#pragma unroll
    for (int k = 0; k < 4; ++k) {
        h[k] = __float2bfloat16_rn(v[k]);
        l[k] = __float2bfloat16_rn(v[k] - __bfloat162float(h[k]));
    }
    __nv_bfloat162 a, b2;
    a.x = h[0]; a.y = h[1]; b2.x = h[2]; b2.y = h[3];
    ((__nv_bfloat162*)hp)[0] = a; ((__nv_bfloat162*)hp)[1] = b2;
    a.x = l[0]; a.y = l[1]; b2.x = l[2]; b2.y = l[3];
    ((__nv_bfloat162*)lp)[0] = a; ((__nv_bfloat162*)lp)[1] = b2;
}

__global__ __launch_bounds__(256, 1)
void attn_kernel(const float* __restrict__ qt, const float* __restrict__ kt,
                 const float* __restrict__ qkv,
                 __nv_bfloat16* __restrict__ oh, __nv_bfloat16* __restrict__ ol) {
    extern __shared__ __align__(128) char smraw[];
    float* smf = (float*)smraw;
    float* Qs   = smf;
    float* Ks   = Qs + 128 * QS_LD;
    float* Vs   = Ks + 128 * QS_LD;
    float* Ss   = Vs + 64 * VS_LD;
    float* rowm = Ss + 64 * SS_LD;
    float* rowl = rowm + 64;
    float* rowa = rowl + 64;

    const int tid = threadIdx.x;
    const int ty  = tid >> 4;
    const int tx  = tid & 15;
    const int b   = blockIdx.z;
    const int h   = blockIdx.y;
    const int s0  = blockIdx.x << 6;
    const int kvh = h >> 2;

    const float* qb = qt + (size_t)((b * NH + h) * HD) * SEQ + s0;
#pragma unroll
    for (int it = 0; it < 8; ++it) {
        int idx = tid + it * 256;
        int d = idx >> 4, c = (idx & 15) << 2;
        *(float4*)&Qs[d * QS_LD + c] = *(const float4*)(qb + (size_t)d * SEQ + c);
    }
    if (tid < 64) { rowm[tid] = -1e30f; rowl[tid] = 0.f; }

    float oacc[4][8];
#pragma unroll
    for (int i = 0; i < 4; ++i)
#pragma unroll
        for (int j = 0; j < 8; ++j) oacc[i][j] = 0.f;

    const float* kb = kt + (size_t)((b * NKV + kvh) * HD) * SEQ;
    const float* vb = qkv + (size_t)b * TP + kvh * GS + (QPG + 1) * HD;

    for (int t0 = 0; t0 < SEQ; t0 += 64) {
        __syncthreads();
#pragma unroll
        for (int it = 0; it < 8; ++it) {
            int idx = tid + it * 256;
            int d = idx >> 4, c = (idx & 15) << 2;
            *(float4*)&Ks[d * QS_LD + c] =
                *(const float4*)(kb + (size_t)d * SEQ + t0 + c);
        }
#pragma unroll
        for (int it = 0; it < 8; ++it) {
            int idx = tid + it * 256;
            int r = idx >> 5, c = (idx & 31) << 2;
            *(float4*)&Vs[r * VS_LD + c] =
                *(const float4*)(vb + (size_t)(t0 + r) * (BATCH * TP) + c);
        }
        __syncthreads();

        float sacc[4][4];
#pragma unroll
        for (int i = 0; i < 4; ++i)
#pragma unroll
            for (int j = 0; j < 4; ++j) sacc[i][j] = 0.f;
#pragma unroll 16
        for (int d = 0; d < 128; ++d) {
            float4 q4 = *(const float4*)&Qs[d * QS_LD + (ty << 2)];
            float4 k4 = *(const float4*)&Ks[d * QS_LD + (tx << 2)];
            float qa[4] = {q4.x, q4.y, q4.z, q4.w};
            float ka[4] = {k4.x, k4.y, k4.z, k4.w};
#pragma unroll
            for (int i = 0; i < 4; ++i)
#pragma unroll
                for (int j = 0; j < 4; ++j)
                    sacc[i][j] += qa[i] * ka[j];
        }
#pragma unroll
        for (int i = 0; i < 4; ++i)
#pragma unroll
            for (int j = 0; j < 4; ++j)
                Ss[((ty << 2) + i) * SS_LD + (tx << 2) + j] = sacc[i][j];
        __syncthreads();

        {
            const int row  = tid >> 2;
            const int part = (tid & 3) << 4;
            float* srow = &Ss[row * SS_LD + part];
            float mloc = srow[0];
#pragma unroll
            for (int c = 1; c < 16; ++c) mloc = fmaxf(mloc, srow[c]);
            mloc = fmaxf(mloc, __shfl_xor_sync(0xffffffffu, mloc, 1));
            mloc = fmaxf(mloc, __shfl_xor_sync(0xffffffffu, mloc, 2));
            float mold = rowm[row];
            float mnew = fmaxf(mold, mloc);
            float sl = 0.f;
#pragma unroll
            for (int c = 0; c < 16; ++c) {
                float p = __expf(srow[c] - mnew);
                srow[c] = p;
                sl += p;
            }
            sl += __shfl_xor_sync(0xffffffffu, sl, 1);
            sl += __shfl_xor_sync(0xffffffffu, sl, 2);
            if ((tid & 3) == 0) {
                float al = __expf(mold - mnew);
                rowa[row] = al;
                rowl[row] = rowl[row] * al + sl;
                rowm[row] = mnew;
            }
        }
        __syncthreads();

        float al[4];
#pragma unroll
        for (int i = 0; i < 4; ++i) al[i] = rowa[(ty << 2) + i];
#pragma unroll
        for (int i = 0; i < 4; ++i)
#pragma unroll
            for (int j = 0; j < 8; ++j) oacc[i][j] *= al[i];

#pragma unroll 8
        for (int kv = 0; kv < 64; ++kv) {
            float4 va = *(const float4*)&Vs[kv * VS_LD + (tx << 2)];
            float4 vc = *(const float4*)&Vs[kv * VS_LD + 64 + (tx << 2)];
            float p[4];
#pragma unroll
            for (int i = 0; i < 4; ++i)
                p[i] = Ss[((ty << 2) + i) * SS_LD + kv];
#pragma unroll
            for (int i = 0; i < 4; ++i) {
                oacc[i][0] += p[i] * va.x;
                oacc[i][1] += p[i] * va.y;
                oacc[i][2] += p[i] * va.z;
                oacc[i][3] += p[i] * va.w;
                oacc[i][4] += p[i] * vc.x;
                oacc[i][5] += p[i] * vc.y;
                oacc[i][6] += p[i] * vc.z;
                oacc[i][7] += p[i] * vc.w;
            }
        }
    }

    // epilogue: normalize and emit hi/lo bf16 split of O
#pragma unroll
    for (int i = 0; i < 4; ++i) {
        float inv = 1.0f / rowl[(ty << 2) + i];
        int m = (s0 + (ty << 2) + i) * BATCH + b;
        size_t base = (size_t)m * EMB + h * HD;
        float v0[4] = {oacc[i][0]*inv, oacc[i][1]*inv, oacc[i][2]*inv, oacc[i][3]*inv};
        float v1[4] = {oacc[i][4]*inv, oacc[i][5]*inv, oacc[i][6]*inv, oacc[i][7]*inv};
        split_store4(oh + base + (tx << 2),      ol + base + (tx << 2),      v0);
        split_store4(oh + base + 64 + (tx << 2), ol + base + 64 + (tx << 2), v1);
    }
}

// ============================================================
extern "C" void kernel_launch(void* const* d_in, const int* in_sizes, int n_in,
                              void* d_out, int out_size) {
    (void)in_sizes; (void)n_in; (void)out_size;
    const float* x      = (const float*)d_in[0];
    const float* w_qkv  = (const float*)d_in[1];
    const float* w_proj = (const float*)d_in[2];
    float* out = (float*)d_out;

    float *qkv, *qt, *kt;
    __nv_bfloat16 *xh, *xl, *wqh, *wql, *wph, *wpl, *oh, *ol;
    cudaGetSymbolAddress((void**)&qkv, g_qkv);
    cudaGetSymbolAddress((void**)&qt,  g_qt);
    cudaGetSymbolAddress((void**)&kt,  g_kt);
    cudaGetSymbolAddress((void**)&xh,  g_xh);
    cudaGetSymbolAddress((void**)&xl,  g_xl);
    cudaGetSymbolAddress((void**)&wqh, g_wqh);
    cudaGetSymbolAddress((void**)&wql, g_wql);
    cudaGetSymbolAddress((void**)&wph, g_wph);
    cudaGetSymbolAddress((void**)&wpl, g_wpl);
    cudaGetSymbolAddress((void**)&oh,  g_oh);
    cudaGetSymbolAddress((void**)&ol,  g_ol);

    cudaFuncSetAttribute(attn_kernel,
                         cudaFuncAttributeMaxDynamicSharedMemorySize, ATT_SMEM);
    cudaFuncSetAttribute(gemm3x,
                         cudaFuncAttributeMaxDynamicSharedMemorySize, GEMM_SMEM);

    // 0) hi/lo splits of GEMM operands
    {
        int n4;
        n4 = M_TOT * HIDDEN / 4;
        split_bf16<<<n4 / 256, 256>>>(x, xh, xl, n4);
        n4 = TP * HIDDEN / 4;
        split_bf16<<<n4 / 256, 256>>>(w_qkv, wqh, wql, n4);
        n4 = HIDDEN * EMB / 4;
        split_bf16<<<n4 / 256, 256>>>(w_proj, wph, wpl, n4);
    }

    // 1) QKV projection (mma.sync bf16x3): qkv[4096,3072] = x @ w_qkv^T
    gemm3x<<<dim3(TP / 128, M_TOT / 128), 256, GEMM_SMEM>>>(
        xh, xl, wqh, wql, qkv, TP, HIDDEN);

    // 2) Q/K transpose to d-major (Q pre-scaled)
    transpose_qk<<<dim3(SEQ / 32, HD / 32, BATCH * 20), 256>>>(qkv, qt, kt);

    // 3) flash attention (writes hi/lo split of O)
    attn_kernel<<<dim3(SEQ / 64, NH, BATCH), 256, ATT_SMEM>>>(qt, kt, qkv, oh, ol);

    // 4) output projection (mma.sync bf16x3): out[4096,2048] = o @ w_proj^T
    gemm3x<<<dim3(EMB / 128, M_TOT / 128), 256, GEMM_SMEM>>>(
        oh, ol, wph, wpl, out, EMB, HIDDEN);
}

// round 8
// speedup vs baseline: 2.9385x; 2.2541x over previous
#include <cuda_runtime.h>
#include <cuda_bf16.h>
#include <cuda_fp16.h>
#include <math.h>
#include <stdint.h>

#define SEQ    2048
#define BATCH  2
#define HIDDEN 2048
#define NKV    4
#define NH     16
#define HD     128
#define QPG    4
#define GS     768            // (QPG+2)*HD
#define TP     3072           // NKV*GS
#define M_TOT  (SEQ*BATCH)    // 4096
#define EMB    2048           // NH*HD

// ---- scratch (device globals: no allocation allowed) ----
__device__ __nv_bfloat16 g_xh [M_TOT * HIDDEN];
__device__ __nv_bfloat16 g_xl [M_TOT * HIDDEN];
__device__ __nv_bfloat16 g_wqh[TP * HIDDEN];
__device__ __nv_bfloat16 g_wql[TP * HIDDEN];
__device__ __nv_bfloat16 g_wph[HIDDEN * EMB];
__device__ __nv_bfloat16 g_wpl[HIDDEN * EMB];
__device__ __nv_bfloat16 g_oh [M_TOT * EMB];
__device__ __nv_bfloat16 g_ol [M_TOT * EMB];
__device__ __half g_qh[BATCH * NH  * SEQ * HD];   // fp16 Q (pre-scaled)
__device__ __half g_kh[BATCH * NKV * SEQ * HD];   // fp16 K
__device__ __half g_vh[BATCH * NKV * SEQ * HD];   // fp16 V

// ============================================================
// helpers
// ============================================================
__device__ __forceinline__ uint32_t smem_u32(const void* p) {
    uint32_t a;
    asm("{ .reg .u64 t; cvta.to.shared.u64 t, %1; cvt.u32.u64 %0, t; }"
        : "=r"(a) : "l"(p));
    return a;
}
__device__ __forceinline__ void cp_async16(uint32_t s, const void* g) {
    asm volatile("cp.async.cg.shared.global [%0], [%1], 16;" :: "r"(s), "l"(g));
}
__device__ __forceinline__ void ldm_x4(uint32_t addr, uint32_t* r) {
    asm volatile("ldmatrix.sync.aligned.m8n8.x4.shared.b16 {%0,%1,%2,%3}, [%4];"
                 : "=r"(r[0]), "=r"(r[1]), "=r"(r[2]), "=r"(r[3]) : "r"(addr));
}
__device__ __forceinline__ void ldm_x4t(uint32_t addr, uint32_t* r) {
    asm volatile("ldmatrix.sync.aligned.m8n8.x4.trans.shared.b16 {%0,%1,%2,%3}, [%4];"
                 : "=r"(r[0]), "=r"(r[1]), "=r"(r[2]), "=r"(r[3]) : "r"(addr));
}
__device__ __forceinline__ void mma16816(float* d, const uint32_t* a,
                                         const uint32_t* b) {
    asm volatile(
        "mma.sync.aligned.m16n8k16.row.col.f32.bf16.bf16.f32 "
        "{%0,%1,%2,%3}, {%4,%5,%6,%7}, {%8,%9}, {%0,%1,%2,%3};"
        : "+f"(d[0]), "+f"(d[1]), "+f"(d[2]), "+f"(d[3])
        : "r"(a[0]), "r"(a[1]), "r"(a[2]), "r"(a[3]), "r"(b[0]), "r"(b[1]));
}
__device__ __forceinline__ void mma16816h(float* d, const uint32_t* a,
                                          const uint32_t* b) {
    asm volatile(
        "mma.sync.aligned.m16n8k16.row.col.f32.f16.f16.f32 "
        "{%0,%1,%2,%3}, {%4,%5,%6,%7}, {%8,%9}, {%0,%1,%2,%3};"
        : "+f"(d[0]), "+f"(d[1]), "+f"(d[2]), "+f"(d[3])
        : "r"(a[0]), "r"(a[1]), "r"(a[2]), "r"(a[3]), "r"(b[0]), "r"(b[1]));
}

// ============================================================
// hi/lo bf16 split (elementwise)
// ============================================================
__global__ void split_bf16(const float* __restrict__ src,
                           __nv_bfloat16* __restrict__ hi,
                           __nv_bfloat16* __restrict__ lo, int n4) {
    int i = blockIdx.x * blockDim.x + threadIdx.x;
    if (i >= n4) return;
    float4 v = ((const float4*)src)[i];
    float a[4] = {v.x, v.y, v.z, v.w};
    __nv_bfloat16 h[4], l[4];
#pragma unroll
    for (int j = 0; j < 4; ++j) {
        h[j] = __float2bfloat16_rn(a[j]);
        l[j] = __float2bfloat16_rn(a[j] - __bfloat162float(h[j]));
    }
    __nv_bfloat162 h01, h23, l01, l23;
    h01.x = h[0]; h01.y = h[1]; h23.x = h[2]; h23.y = h[3];
    l01.x = l[0]; l01.y = l[1]; l23.x = l[2]; l23.y = l[3];
    ((__nv_bfloat162*)hi)[2*i]   = h01;
    ((__nv_bfloat162*)hi)[2*i+1] = h23;
    ((__nv_bfloat162*)lo)[2*i]   = l01;
    ((__nv_bfloat162*)lo)[2*i+1] = l23;
}

// ============================================================
// bf16x3 GEMM (mma.sync).  mode 0: fp32 C.  mode 1: fp16 QKV scatter
// (q pre-scaled by 1/sqrt(HD)) into g_qh/g_kh/g_vh layouts.
// ============================================================
#define GSTAGES 4
#define GBK 32
#define GPITCH 80
#define GTILE_B (128 * GPITCH)
#define GSTAGE_B (4 * GTILE_B)
#define GEMM_SMEM (GSTAGES * GSTAGE_B)     // 163840

__device__ __forceinline__ void qkv_store(__half* qh, __half* kh, __half* vh,
                                          int r, int c, float v0, float v1) {
    const int s = r >> 1, bb = r & 1;
    const int kvh = c / GS, pos = c - kvh * GS;
    if (pos < QPG * HD) {
        const int hh = kvh * QPG + (pos >> 7), d = pos & 127;
        const float SC = 0.08838834764831845f;
        *(__half2*)(qh + ((size_t)(bb * NH + hh) * SEQ + s) * HD + d) =
            __floats2half2_rn(v0 * SC, v1 * SC);
    } else if (pos < (QPG + 1) * HD) {
        const int d = pos - QPG * HD;
        *(__half2*)(kh + ((size_t)(bb * NKV + kvh) * SEQ + s) * HD + d) =
            __floats2half2_rn(v0, v1);
    } else {
        const int d = pos - (QPG + 1) * HD;
        *(__half2*)(vh + ((size_t)(bb * NKV + kvh) * SEQ + s) * HD + d) =
            __floats2half2_rn(v0, v1);
    }
}

__device__ __forceinline__ void gemm_load_stage(
    uint32_t sb, int it, int tid,
    const __nv_bfloat16* Ah, const __nv_bfloat16* Al,
    const __nv_bfloat16* Bh, const __nv_bfloat16* Bl,
    int m0, int n0, int K) {
    const uint32_t st = sb + (it % GSTAGES) * GSTAGE_B;
    const int k0 = it * GBK;
    const __nv_bfloat16* srcs[4] = {Ah, Al, Bh, Bl};
    const int r0[4] = {m0, m0, n0, n0};
#pragma unroll
    for (int t = 0; t < 8; ++t) {
        int chunk = tid + t * 256;
        int tbl = chunk >> 9;
        int within = chunk & 511;
        int row = within >> 2, c = within & 3;
        uint32_t dst = st + tbl * GTILE_B + row * GPITCH + c * 16;
        cp_async16(dst, srcs[tbl] + (size_t)(r0[tbl] + row) * K + k0 + c * 8);
    }
    asm volatile("cp.async.commit_group;" ::: "memory");
}

__global__ __launch_bounds__(256, 1)
void gemm3x(const __nv_bfloat16* __restrict__ Ah, const __nv_bfloat16* __restrict__ Al,
            const __nv_bfloat16* __restrict__ Bh, const __nv_bfloat16* __restrict__ Bl,
            float* __restrict__ C, int N, int K, int mode,
            __half* qh, __half* kh, __half* vh) {
    extern __shared__ __align__(128) char smraw[];
    const uint32_t sb = smem_u32(smraw);
    const int tid  = threadIdx.x;
    const int lane = tid & 31;
    const int wid  = tid >> 5;
    const int wm   = wid & 1;
    const int wn   = wid >> 1;
    const int m0   = blockIdx.y << 7;
    const int n0   = blockIdx.x << 7;

    float acc[4][4][4];
#pragma unroll
    for (int i = 0; i < 4; ++i)
#pragma unroll
        for (int j = 0; j < 4; ++j)
#pragma unroll
            for (int q = 0; q < 4; ++q) acc[i][j][q] = 0.f;

    const int T = K / GBK;
    for (int it = 0; it < GSTAGES - 1; ++it)
        gemm_load_stage(sb, it, tid, Ah, Al, Bh, Bl, m0, n0, K);

    const uint32_t aRow = (wm << 6) + (lane & 15);
    const uint32_t aCol = (lane >> 4) << 4;
    const uint32_t bRow = (wn << 5) + (((lane >> 4) & 1) << 3) + (lane & 7);
    const uint32_t bCol = ((lane >> 3) & 1) << 4;

    for (int ci = 0; ci < T; ++ci) {
        asm volatile("cp.async.wait_group %0;" :: "n"(GSTAGES - 2) : "memory");
        __syncthreads();
        const uint32_t st = sb + (ci % GSTAGES) * GSTAGE_B;

#pragma unroll
        for (int ac = 0; ac < 2; ++ac) {
            const uint32_t aBase = st + ac * GTILE_B;
#pragma unroll
            for (int k16 = 0; k16 < 2; ++k16) {
                uint32_t afr[4][4];
#pragma unroll
                for (int mi = 0; mi < 4; ++mi)
                    ldm_x4(aBase + (aRow + mi * 16) * GPITCH + k16 * 32 + aCol,
                           afr[mi]);
                const int nbc = (ac == 0) ? 2 : 1;
#pragma unroll
                for (int bc = 0; bc < 2; ++bc) {
                    if (bc >= nbc) break;
                    const uint32_t bBase = st + (2 + bc) * GTILE_B;
#pragma unroll
                    for (int p = 0; p < 2; ++p) {
                        uint32_t bfr[4];
                        ldm_x4(bBase + (bRow + p * 16) * GPITCH + k16 * 32 + bCol,
                               bfr);
#pragma unroll
                        for (int mi = 0; mi < 4; ++mi) {
                            mma16816(acc[mi][p * 2],     afr[mi], bfr);
                            mma16816(acc[mi][p * 2 + 1], afr[mi], bfr + 2);
                        }
                    }
                }
            }
        }
        __syncthreads();
        if (ci + GSTAGES - 1 < T)
            gemm_load_stage(sb, ci + GSTAGES - 1, tid, Ah, Al, Bh, Bl, m0, n0, K);
        else
            asm volatile("cp.async.commit_group;" ::: "memory");
    }

    const int rBase = m0 + (wm << 6) + (lane >> 2);
    const int cBase = n0 + (wn << 5) + ((lane & 3) << 1);
    if (mode == 0) {
#pragma unroll
        for (int mi = 0; mi < 4; ++mi)
#pragma unroll
            for (int nj = 0; nj < 4; ++nj) {
                int r = rBase + mi * 16;
                int c = cBase + nj * 8;
                *(float2*)&C[(size_t)r * N + c] =
                    make_float2(acc[mi][nj][0], acc[mi][nj][1]);
                *(float2*)&C[(size_t)(r + 8) * N + c] =
                    make_float2(acc[mi][nj][2], acc[mi][nj][3]);
            }
    } else {
#pragma unroll
        for (int mi = 0; mi < 4; ++mi)
#pragma unroll
            for (int nj = 0; nj < 4; ++nj) {
                int r = rBase + mi * 16;
                int c = cBase + nj * 8;
                qkv_store(qh, kh, vh, r,     c, acc[mi][nj][0], acc[mi][nj][1]);
                qkv_store(qh, kh, vh, r + 8, c, acc[mi][nj][2], acc[mi][nj][3]);
            }
    }
}

// ============================================================
// fp16 tensor-core flash attention.
// CTA = (b, h, 128-q tile); KV tile 64, double-buffered cp.async.
// Q in registers; P kept in registers (S-frag == A-frag identity);
// V via ldmatrix.trans. O epilogue emits hi/lo bf16.
// ============================================================
#define AKV 64
#define APITCH 272                     // bytes per 128-half row (+16B skew)
#define AQ_BYTES  (128 * APITCH)       // 34816
#define AKV_BYTES (AKV * APITCH)       // 17408
#define SM_K(s) (AQ_BYTES + (s) * AKV_BYTES)
#define SM_V(s) (AQ_BYTES + 2 * AKV_BYTES + (s) * AKV_BYTES)
#define ATTN_SMEM (AQ_BYTES + 4 * AKV_BYTES)   // 104448

__device__ __forceinline__ void attn_load_kv(uint32_t sb, int t, int s, int tid,
                                             const __half* kb, const __half* vb) {
    const uint32_t ks = sb + SM_K(s), vs = sb + SM_V(s);
    const __half* kt = kb + (size_t)t * AKV * HD;
    const __half* vt = vb + (size_t)t * AKV * HD;
#pragma unroll
    for (int i = 0; i < 4; ++i) {
        int chunk = tid + i * 256;          // 0..1023
        int row = chunk >> 4, cc = chunk & 15;
        cp_async16(ks + row * APITCH + cc * 16, kt + row * HD + cc * 8);
        cp_async16(vs + row * APITCH + cc * 16, vt + row * HD + cc * 8);
    }
}

__device__ __forceinline__ void store2_hl(__nv_bfloat16* oh, __nv_bfloat16* ol,
                                          size_t off, float v0, float v1) {
    __nv_bfloat16 h0 = __float2bfloat16_rn(v0);
    __nv_bfloat16 h1 = __float2bfloat16_rn(v1);
    __nv_bfloat162 hh; hh.x = h0; hh.y = h1;
    __nv_bfloat162 ee;
    ee.x = __float2bfloat16_rn(v0 - __bfloat162float(h0));
    ee.y = __float2bfloat16_rn(v1 - __bfloat162float(h1));
    *(__nv_bfloat162*)(oh + off) = hh;
    *(__nv_bfloat162*)(ol + off) = ee;
}

__global__ __launch_bounds__(256, 1)
void attn_fp16(const __half* __restrict__ qh, const __half* __restrict__ kh,
               const __half* __restrict__ vh,
               __nv_bfloat16* __restrict__ oh, __nv_bfloat16* __restrict__ ol) {
    extern __shared__ __align__(128) char smraw[];
    const uint32_t sb = smem_u32(smraw);
    const int tid = threadIdx.x, lane = tid & 31, w = tid >> 5;
    const int b = blockIdx.z, h = blockIdx.y, s0 = blockIdx.x << 7;
    const int kvh = h >> 2;
    const __half* qb = qh + ((size_t)(b * NH + h) * SEQ + s0) * HD;
    const __half* kb = kh + (size_t)(b * NKV + kvh) * SEQ * HD;
    const __half* vb = vh + (size_t)(b * NKV + kvh) * SEQ * HD;

    // Q tile (128 rows x 256B) + first KV tile, one commit group
#pragma unroll
    for (int i = 0; i < 8; ++i) {
        int chunk = tid + i * 256;          // 0..2047
        int row = chunk >> 4, cc = chunk & 15;
        cp_async16(sb + row * APITCH + cc * 16, qb + row * HD + cc * 8);
    }
    attn_load_kv(sb, 0, 0, tid, kb, vb);
    asm volatile("cp.async.commit_group;" ::: "memory");

    float o[16][4];
#pragma unroll
    for (int j = 0; j < 16; ++j)
#pragma unroll
        for (int q = 0; q < 4; ++q) o[j][q] = 0.f;
    float m0 = -1e30f, m1 = -1e30f, l0 = 0.f, l1 = 0.f;
    uint32_t qfr[8][4];

    const uint32_t kbRow = (((lane >> 4) & 1) << 3) + (lane & 7);
    const uint32_t kbCol = ((lane >> 3) & 1) << 4;
    const uint32_t vbRow = (((lane >> 3) & 1) << 3) + (lane & 7);
    const uint32_t vbCol = ((lane >> 4) & 1) << 4;

    const int NT = SEQ / AKV;   // 32
    for (int t = 0; t < NT; ++t) {
        if (t + 1 < NT) attn_load_kv(sb, t + 1, (t + 1) & 1, tid, kb, vb);
        asm volatile("cp.async.commit_group;" ::: "memory");
        asm volatile("cp.async.wait_group 1;" ::: "memory");
        __syncthreads();
        if (t == 0) {
            const uint32_t qa = sb + (w * 16 + (lane & 15)) * APITCH +
                                ((lane >> 4) << 4);
#pragma unroll
            for (int k16 = 0; k16 < 8; ++k16) ldm_x4(qa + k16 * 32, qfr[k16]);
        }
        const uint32_t ksm = sb + SM_K(t & 1), vsm = sb + SM_V(t & 1);

        // ---- S = Q K^T (pre-scaled Q) ----
        float sv[8][4];
#pragma unroll
        for (int j = 0; j < 8; ++j)
#pragma unroll
            for (int q = 0; q < 4; ++q) sv[j][q] = 0.f;
#pragma unroll
        for (int k16 = 0; k16 < 8; ++k16) {
#pragma unroll
            for (int j2 = 0; j2 < 4; ++j2) {
                uint32_t bfr[4];
                ldm_x4(ksm + (j2 * 16 + kbRow) * APITCH + k16 * 32 + kbCol, bfr);
                mma16816h(sv[2 * j2],     qfr[k16], bfr);
                mma16816h(sv[2 * j2 + 1], qfr[k16], bfr + 2);
            }
        }

        // ---- online softmax (rows r=lane>>2 and r+8) ----
        float rmax0 = -1e30f, rmax1 = -1e30f;
#pragma unroll
        for (int j = 0; j < 8; ++j) {
            rmax0 = fmaxf(rmax0, fmaxf(sv[j][0], sv[j][1]));
            rmax1 = fmaxf(rmax1, fmaxf(sv[j][2], sv[j][3]));
        }
        rmax0 = fmaxf(rmax0, __shfl_xor_sync(0xffffffffu, rmax0, 1));
        rmax0 = fmaxf(rmax0, __shfl_xor_sync(0xffffffffu, rmax0, 2));
        rmax1 = fmaxf(rmax1, __shfl_xor_sync(0xffffffffu, rmax1, 1));
        rmax1 = fmaxf(rmax1, __shfl_xor_sync(0xffffffffu, rmax1, 2));
        const float mn0 = fmaxf(m0, rmax0), mn1 = fmaxf(m1, rmax1);
        const float a0 = __expf(m0 - mn0), a1 = __expf(m1 - mn1);
        m0 = mn0; m1 = mn1;
        uint32_t pa[8][2];
        float ps0 = 0.f, ps1 = 0.f;
#pragma unroll
        for (int j = 0; j < 8; ++j) {
            float p00 = __expf(sv[j][0] - m0), p01 = __expf(sv[j][1] - m0);
            float p10 = __expf(sv[j][2] - m1), p11 = __expf(sv[j][3] - m1);
            ps0 += p00 + p01; ps1 += p10 + p11;
            __half2 q0 = __floats2half2_rn(p00, p01);
            __half2 q1 = __floats2half2_rn(p10, p11);
            pa[j][0] = *(uint32_t*)&q0;
            pa[j][1] = *(uint32_t*)&q1;
        }
        l0 = l0 * a0 + ps0; l1 = l1 * a1 + ps1;
#pragma unroll
        for (int j = 0; j < 16; ++j) {
            o[j][0] *= a0; o[j][1] *= a0; o[j][2] *= a1; o[j][3] *= a1;
        }

        // ---- O += P V  (P frags from registers, V via ldmatrix.trans) ----
#pragma unroll
        for (int kk = 0; kk < 4; ++kk) {
            uint32_t afr2[4] = {pa[2 * kk][0], pa[2 * kk][1],
                                pa[2 * kk + 1][0], pa[2 * kk + 1][1]};
#pragma unroll
            for (int j2 = 0; j2 < 8; ++j2) {
                uint32_t bfr[4];
                ldm_x4t(vsm + (kk * 16 + vbRow) * APITCH + j2 * 32 + vbCol, bfr);
                mma16816h(o[2 * j2],     afr2, bfr);
                mma16816h(o[2 * j2 + 1], afr2, bfr + 2);
            }
        }
        __syncthreads();
    }

    // ---- epilogue: normalize, hi/lo bf16 split ----
    l0 += __shfl_xor_sync(0xffffffffu, l0, 1);
    l0 += __shfl_xor_sync(0xffffffffu, l0, 2);
    l1 += __shfl_xor_sync(0xffffffffu, l1, 1);
    l1 += __shfl_xor_sync(0xffffffffu, l1, 2);
    const float i0 = 1.f / l0, i1 = 1.f / l1;
    const int qr0 = s0 + w * 16 + (lane >> 2);
    const size_t base0 = (size_t)(qr0 * BATCH + b) * EMB + h * HD;
    const size_t base1 = (size_t)((qr0 + 8) * BATCH + b) * EMB + h * HD;
#pragma unroll
    for (int j = 0; j < 16; ++j) {
        const int d = j * 8 + ((lane & 3) << 1);
        store2_hl(oh, ol, base0 + d, o[j][0] * i0, o[j][1] * i0);
        store2_hl(oh, ol, base1 + d, o[j][2] * i1, o[j][3] * i1);
    }
}

// ============================================================
extern "C" void kernel_launch(void* const* d_in, const int* in_sizes, int n_in,
                              void* d_out, int out_size) {
    (void)in_sizes; (void)n_in; (void)out_size;
    const float* x      = (const float*)d_in[0];
    const float* w_qkv  = (const float*)d_in[1];
    const float* w_proj = (const float*)d_in[2];
    float* out = (float*)d_out;

    __nv_bfloat16 *xh, *xl, *wqh, *wql, *wph, *wpl, *oh, *ol;
    __half *qhp, *khp, *vhp;
    cudaGetSymbolAddress((void**)&xh,  g_xh);
    cudaGetSymbolAddress((void**)&xl,  g_xl);
    cudaGetSymbolAddress((void**)&wqh, g_wqh);
    cudaGetSymbolAddress((void**)&wql, g_wql);
    cudaGetSymbolAddress((void**)&wph, g_wph);
    cudaGetSymbolAddress((void**)&wpl, g_wpl);
    cudaGetSymbolAddress((void**)&oh,  g_oh);
    cudaGetSymbolAddress((void**)&ol,  g_ol);
    cudaGetSymbolAddress((void**)&qhp, g_qh);
    cudaGetSymbolAddress((void**)&khp, g_kh);
    cudaGetSymbolAddress((void**)&vhp, g_vh);

    cudaFuncSetAttribute(gemm3x,
                         cudaFuncAttributeMaxDynamicSharedMemorySize, GEMM_SMEM);
    cudaFuncSetAttribute(attn_fp16,
                         cudaFuncAttributeMaxDynamicSharedMemorySize, ATTN_SMEM);

    // 0) hi/lo splits of GEMM operands
    {
        int n4;
        n4 = M_TOT * HIDDEN / 4;
        split_bf16<<<n4 / 256, 256>>>(x, xh, xl, n4);
        n4 = TP * HIDDEN / 4;
        split_bf16<<<n4 / 256, 256>>>(w_qkv, wqh, wql, n4);
        n4 = HIDDEN * EMB / 4;
        split_bf16<<<n4 / 256, 256>>>(w_proj, wph, wpl, n4);
    }

    // 1) QKV projection -> fp16 q/k/v (q pre-scaled), fused scatter epilogue
    gemm3x<<<dim3(TP / 128, M_TOT / 128), 256, GEMM_SMEM>>>(
        xh, xl, wqh, wql, nullptr, TP, HIDDEN, 1, qhp, khp, vhp);

    // 2) fp16 flash attention (writes hi/lo bf16 split of O)
    attn_fp16<<<dim3(SEQ / 128, NH, BATCH), 256, ATTN_SMEM>>>(
        qhp, khp, vhp, oh, ol);

    // 3) output projection (bf16x3): out[4096,2048] = O @ w_proj^T
    gemm3x<<<dim3(EMB / 128, M_TOT / 128), 256, GEMM_SMEM>>>(
        oh, ol, wph, wpl, out, EMB, HIDDEN, 0, nullptr, nullptr, nullptr);
}

// round 11
// speedup vs baseline: 4.3028x; 1.4643x over previous
#include <cuda_runtime.h>
#include <cuda_fp16.h>
#include <math.h>
#include <stdint.h>

#define SEQ    2048
#define BATCH  2
#define HIDDEN 2048
#define NKV    4
#define NH     16
#define HD     128
#define QPG    4
#define GS     768            // (QPG+2)*HD
#define TP     3072           // NKV*GS
#define M_TOT  (SEQ*BATCH)    // 4096
#define EMB    2048           // NH*HD

// ---- scratch (device globals: no allocation allowed) ----
__device__ __half g_xh [M_TOT * HIDDEN];        // x hi/lo (fp16)
__device__ __half g_xl [M_TOT * HIDDEN];
__device__ __half g_wq [TP * HIDDEN];           // w_qkv fp16
__device__ __half g_wp [HIDDEN * EMB];          // w_proj fp16
__device__ __half g_oh [M_TOT * EMB];           // attn out hi/lo (fp16)
__device__ __half g_ol [M_TOT * EMB];
__device__ __half g_qh[BATCH * NH  * SEQ * HD]; // fp16 Q (pre-scaled)
__device__ __half g_kh[BATCH * NKV * SEQ * HD]; // fp16 K
__device__ __half g_vh[BATCH * NKV * SEQ * HD]; // fp16 V

// ============================================================
// helpers
// ============================================================
__device__ __forceinline__ uint32_t smem_u32(const void* p) {
    uint32_t a;
    asm("{ .reg .u64 t; cvta.to.shared.u64 t, %1; cvt.u32.u64 %0, t; }"
        : "=r"(a) : "l"(p));
    return a;
}
__device__ __forceinline__ void cp_async16(uint32_t s, const void* g) {
    asm volatile("cp.async.cg.shared.global [%0], [%1], 16;" :: "r"(s), "l"(g));
}
__device__ __forceinline__ void ldm_x4(uint32_t addr, uint32_t* r) {
    asm volatile("ldmatrix.sync.aligned.m8n8.x4.shared.b16 {%0,%1,%2,%3}, [%4];"
                 : "=r"(r[0]), "=r"(r[1]), "=r"(r[2]), "=r"(r[3]) : "r"(addr));
}
__device__ __forceinline__ void ldm_x4t(uint32_t addr, uint32_t* r) {
    asm volatile("ldmatrix.sync.aligned.m8n8.x4.trans.shared.b16 {%0,%1,%2,%3}, [%4];"
                 : "=r"(r[0]), "=r"(r[1]), "=r"(r[2]), "=r"(r[3]) : "r"(addr));
}
__device__ __forceinline__ void mma16816h(float* d, const uint32_t* a,
                                          const uint32_t* b) {
    asm volatile(
        "mma.sync.aligned.m16n8k16.row.col.f32.f16.f16.f32 "
        "{%0,%1,%2,%3}, {%4,%5,%6,%7}, {%8,%9}, {%0,%1,%2,%3};"
        : "+f"(d[0]), "+f"(d[1]), "+f"(d[2]), "+f"(d[3])
        : "r"(a[0]), "r"(a[1]), "r"(a[2]), "r"(a[3]), "r"(b[0]), "r"(b[1]));
}

// ============================================================
// prologue conversions
// ============================================================
__global__ void split_half(const float* __restrict__ src,
                           __half* __restrict__ hi, __half* __restrict__ lo,
                           int n4) {
    int i = blockIdx.x * blockDim.x + threadIdx.x;
    if (i >= n4) return;
    float4 v = ((const float4*)src)[i];
    float a[4] = {v.x, v.y, v.z, v.w};
    __half h[4], l[4];
#pragma unroll
    for (int j = 0; j < 4; ++j) {
        h[j] = __float2half_rn(a[j]);
        l[j] = __float2half_rn(a[j] - __half2float(h[j]));
    }
    __half2 p0, p1;
    p0.x = h[0]; p0.y = h[1]; p1.x = h[2]; p1.y = h[3];
    ((__half2*)hi)[2*i] = p0; ((__half2*)hi)[2*i+1] = p1;
    p0.x = l[0]; p0.y = l[1]; p1.x = l[2]; p1.y = l[3];
    ((__half2*)lo)[2*i] = p0; ((__half2*)lo)[2*i+1] = p1;
}

__global__ void conv_half(const float* __restrict__ src,
                          __half* __restrict__ dst, int n4) {
    int i = blockIdx.x * blockDim.x + threadIdx.x;
    if (i >= n4) return;
    float4 v = ((const float4*)src)[i];
    __half2 p0 = __floats2half2_rn(v.x, v.y);
    __half2 p1 = __floats2half2_rn(v.z, v.w);
    ((__half2*)dst)[2*i] = p0; ((__half2*)dst)[2*i+1] = p1;
}

// ============================================================
// fp16 A-split GEMM: C = (Ah+Al)[M][K] * B[N][K]^T, fp32 accum.
// 128x128 CTA, BK=32, 3-stage cp.async, 2 CTAs/SM.
// mode 0: fp32 C.  mode 1: fp16 QKV scatter (q pre-scaled).
// ============================================================
#define GSTAGES 3
#define GBK 32
#define GPITCH 80
#define GTILE_B (128 * GPITCH)             // 10240
#define GSTAGE_B (3 * GTILE_B)             // Ah, Al, B = 30720
#define GEMM_SMEM (GSTAGES * GSTAGE_B)     // 92160

__device__ __forceinline__ void qkv_store(__half* qh, __half* kh, __half* vh,
                                          int r, int c, float v0, float v1) {
    const int s = r >> 1, bb = r & 1;
    const int kvh = c / GS, pos = c - kvh * GS;
    if (pos < QPG * HD) {
        const int hh = kvh * QPG + (pos >> 7), d = pos & 127;
        const float SC = 0.08838834764831845f;
        *(__half2*)(qh + ((size_t)(bb * NH + hh) * SEQ + s) * HD + d) =
            __floats2half2_rn(v0 * SC, v1 * SC);
    } else if (pos < (QPG + 1) * HD) {
        const int d = pos - QPG * HD;
        *(__half2*)(kh + ((size_t)(bb * NKV + kvh) * SEQ + s) * HD + d) =
            __floats2half2_rn(v0, v1);
    } else {
        const int d = pos - (QPG + 1) * HD;
        *(__half2*)(vh + ((size_t)(bb * NKV + kvh) * SEQ + s) * HD + d) =
            __floats2half2_rn(v0, v1);
    }
}

__device__ __forceinline__ void gemm_load_stage(
    uint32_t sb, int it, int tid,
    const __half* Ah, const __half* Al, const __half* B,
    int m0, int n0, int K) {
    const uint32_t st = sb + (it % GSTAGES) * GSTAGE_B;
    const int k0 = it * GBK;
    const __half* srcs[3] = {Ah, Al, B};
    const int r0[3] = {m0, m0, n0};
#pragma unroll
    for (int t = 0; t < 6; ++t) {
        int chunk = tid + t * 256;          // 0..1535
        int tbl = chunk >> 9;               // 512 16B-chunks per tile
        int within = chunk & 511;
        int row = within >> 2, c = within & 3;
        uint32_t dst = st + tbl * GTILE_B + row * GPITCH + c * 16;
        cp_async16(dst, srcs[tbl] + (size_t)(r0[tbl] + row) * K + k0 + c * 8);
    }
    asm volatile("cp.async.commit_group;" ::: "memory");
}

__global__ __launch_bounds__(256, 2)
void gemm2c(const __half* __restrict__ Ah, const __half* __restrict__ Al,
            const __half* __restrict__ B,
            float* __restrict__ C, int N, int K, int mode,
            __half* qh, __half* kh, __half* vh) {
    extern __shared__ __align__(128) char smraw[];
    const uint32_t sb = smem_u32(smraw);
    const int tid  = threadIdx.x;
    const int lane = tid & 31;
    const int wid  = tid >> 5;
    const int wm   = wid & 1;
    const int wn   = wid >> 1;
    const int m0   = blockIdx.y << 7;
    const int n0   = blockIdx.x << 7;

    float acc[4][4][4];
#pragma unroll
    for (int i = 0; i < 4; ++i)
#pragma unroll
        for (int j = 0; j < 4; ++j)
#pragma unroll
            for (int q = 0; q < 4; ++q) acc[i][j][q] = 0.f;

    const int T = K / GBK;
    for (int it = 0; it < GSTAGES - 1; ++it)
        gemm_load_stage(sb, it, tid, Ah, Al, B, m0, n0, K);

    const uint32_t aRow = (wm << 6) + (lane & 15);
    const uint32_t aCol = (lane >> 4) << 4;
    const uint32_t bRow = (wn << 5) + (((lane >> 4) & 1) << 3) + (lane & 7);
    const uint32_t bCol = ((lane >> 3) & 1) << 4;

    for (int ci = 0; ci < T; ++ci) {
        asm volatile("cp.async.wait_group %0;" :: "n"(GSTAGES - 2) : "memory");
        __syncthreads();
        const uint32_t st = sb + (ci % GSTAGES) * GSTAGE_B;
        const uint32_t bBase = st + 2 * GTILE_B;

#pragma unroll
        for (int ac = 0; ac < 2; ++ac) {
            const uint32_t aBase = st + ac * GTILE_B;
#pragma unroll
            for (int k16 = 0; k16 < 2; ++k16) {
                uint32_t afr[4][4];
#pragma unroll
                for (int mi = 0; mi < 4; ++mi)
                    ldm_x4(aBase + (aRow + mi * 16) * GPITCH + k16 * 32 + aCol,
                           afr[mi]);
#pragma unroll
                for (int p = 0; p < 2; ++p) {
                    uint32_t bfr[4];
                    ldm_x4(bBase + (bRow + p * 16) * GPITCH + k16 * 32 + bCol,
                           bfr);
#pragma unroll
                    for (int mi = 0; mi < 4; ++mi) {
                        mma16816h(acc[mi][p * 2],     afr[mi], bfr);
                        mma16816h(acc[mi][p * 2 + 1], afr[mi], bfr + 2);
                    }
                }
            }
        }
        __syncthreads();
        if (ci + GSTAGES - 1 < T)
            gemm_load_stage(sb, ci + GSTAGES - 1, tid, Ah, Al, B, m0, n0, K);
        else
            asm volatile("cp.async.commit_group;" ::: "memory");
    }

    const int rBase = m0 + (wm << 6) + (lane >> 2);
    const int cBase = n0 + (wn << 5) + ((lane & 3) << 1);
    if (mode == 0) {
#pragma unroll
        for (int mi = 0; mi < 4; ++mi)
#pragma unroll
            for (int nj = 0; nj < 4; ++nj) {
                int r = rBase + mi * 16;
                int c = cBase + nj * 8;
                *(float2*)&C[(size_t)r * N + c] =
                    make_float2(acc[mi][nj][0], acc[mi][nj][1]);
                *(float2*)&C[(size_t)(r + 8) * N + c] =
                    make_float2(acc[mi][nj][2], acc[mi][nj][3]);
            }
    } else {
#pragma unroll
        for (int mi = 0; mi < 4; ++mi)
#pragma unroll
            for (int nj = 0; nj < 4; ++nj) {
                int r = rBase + mi * 16;
                int c = cBase + nj * 8;
                qkv_store(qh, kh, vh, r,     c, acc[mi][nj][0], acc[mi][nj][1]);
                qkv_store(qh, kh, vh, r + 8, c, acc[mi][nj][2], acc[mi][nj][3]);
            }
    }
}

// ============================================================
// fp16 tensor-core flash attention (unchanged from 1265us pass).
// Epilogue emits hi/lo fp16 split of O for GEMM2's A operand.
// ============================================================
#define AKV 64
#define APITCH 272
#define AQ_BYTES  (128 * APITCH)
#define AKV_BYTES (AKV * APITCH)
#define SM_K(s) (AQ_BYTES + (s) * AKV_BYTES)
#define SM_V(s) (AQ_BYTES + 2 * AKV_BYTES + (s) * AKV_BYTES)
#define ATTN_SMEM (AQ_BYTES + 4 * AKV_BYTES)   // 104448

__device__ __forceinline__ void attn_load_kv(uint32_t sb, int t, int s, int tid,
                                             const __half* kb, const __half* vb) {
    const uint32_t ks = sb + SM_K(s), vs = sb + SM_V(s);
    const __half* kt = kb + (size_t)t * AKV * HD;
    const __half* vt = vb + (size_t)t * AKV * HD;
#pragma unroll
    for (int i = 0; i < 4; ++i) {
        int chunk = tid + i * 256;
        int row = chunk >> 4, cc = chunk & 15;
        cp_async16(ks + row * APITCH + cc * 16, kt + row * HD + cc * 8);
        cp_async16(vs + row * APITCH + cc * 16, vt + row * HD + cc * 8);
    }
}

__device__ __forceinline__ void store2_hl(__half* oh, __half* ol,
                                          size_t off, float v0, float v1) {
    __half h0 = __float2half_rn(v0);
    __half h1 = __float2half_rn(v1);
    __half2 hh; hh.x = h0; hh.y = h1;
    __half2 ee;
    ee.x = __float2half_rn(v0 - __half2float(h0));
    ee.y = __float2half_rn(v1 - __half2float(h1));
    *(__half2*)(oh + off) = hh;
    *(__half2*)(ol + off) = ee;
}

__global__ __launch_bounds__(256, 1)
void attn_fp16(const __half* __restrict__ qh, const __half* __restrict__ kh,
               const __half* __restrict__ vh,
               __half* __restrict__ oh, __half* __restrict__ ol) {
    extern __shared__ __align__(128) char smraw[];
    const uint32_t sb = smem_u32(smraw);
    const int tid = threadIdx.x, lane = tid & 31, w = tid >> 5;
    const int b = blockIdx.z, h = blockIdx.y, s0 = blockIdx.x << 7;
    const int kvh = h >> 2;
    const __half* qb = qh + ((size_t)(b * NH + h) * SEQ + s0) * HD;
    const __half* kb = kh + (size_t)(b * NKV + kvh) * SEQ * HD;
    const __half* vb = vh + (size_t)(b * NKV + kvh) * SEQ * HD;

#pragma unroll
    for (int i = 0; i < 8; ++i) {
        int chunk = tid + i * 256;
        int row = chunk >> 4, cc = chunk & 15;
        cp_async16(sb + row * APITCH + cc * 16, qb + row * HD + cc * 8);
    }
    attn_load_kv(sb, 0, 0, tid, kb, vb);
    asm volatile("cp.async.commit_group;" ::: "memory");

    float o[16][4];
#pragma unroll
    for (int j = 0; j < 16; ++j)
#pragma unroll
        for (int q = 0; q < 4; ++q) o[j][q] = 0.f;
    float m0 = -1e30f, m1 = -1e30f, l0 = 0.f, l1 = 0.f;
    uint32_t qfr[8][4];

    const uint32_t kbRow = (((lane >> 4) & 1) << 3) + (lane & 7);
    const uint32_t kbCol = ((lane >> 3) & 1) << 4;
    const uint32_t vbRow = (((lane >> 3) & 1) << 3) + (lane & 7);
    const uint32_t vbCol = ((lane >> 4) & 1) << 4;

    const int NT = SEQ / AKV;
    for (int t = 0; t < NT; ++t) {
        if (t + 1 < NT) attn_load_kv(sb, t + 1, (t + 1) & 1, tid, kb, vb);
        asm volatile("cp.async.commit_group;" ::: "memory");
        asm volatile("cp.async.wait_group 1;" ::: "memory");
        __syncthreads();
        if (t == 0) {
            const uint32_t qa = sb + (w * 16 + (lane & 15)) * APITCH +
                                ((lane >> 4) << 4);
#pragma unroll
            for (int k16 = 0; k16 < 8; ++k16) ldm_x4(qa + k16 * 32, qfr[k16]);
        }
        const uint32_t ksm = sb + SM_K(t & 1), vsm = sb + SM_V(t & 1);

        float sv[8][4];
#pragma unroll
        for (int j = 0; j < 8; ++j)
#pragma unroll
            for (int q = 0; q < 4; ++q) sv[j][q] = 0.f;
#pragma unroll
        for (int k16 = 0; k16 < 8; ++k16) {
#pragma unroll
            for (int j2 = 0; j2 < 4; ++j2) {
                uint32_t bfr[4];
                ldm_x4(ksm + (j2 * 16 + kbRow) * APITCH + k16 * 32 + kbCol, bfr);
                mma16816h(sv[2 * j2],     qfr[k16], bfr);
                mma16816h(sv[2 * j2 + 1], qfr[k16], bfr + 2);
            }
        }

        float rmax0 = -1e30f, rmax1 = -1e30f;
#pragma unroll
        for (int j = 0; j < 8; ++j) {
            rmax0 = fmaxf(rmax0, fmaxf(sv[j][0], sv[j][1]));
            rmax1 = fmaxf(rmax1, fmaxf(sv[j][2], sv[j][3]));
        }
        rmax0 = fmaxf(rmax0, __shfl_xor_sync(0xffffffffu, rmax0, 1));
        rmax0 = fmaxf(rmax0, __shfl_xor_sync(0xffffffffu, rmax0, 2));
        rmax1 = fmaxf(rmax1, __shfl_xor_sync(0xffffffffu, rmax1, 1));
        rmax1 = fmaxf(rmax1, __shfl_xor_sync(0xffffffffu, rmax1, 2));
        const float mn0 = fmaxf(m0, rmax0), mn1 = fmaxf(m1, rmax1);
        const float a0 = __expf(m0 - mn0), a1 = __expf(m1 - mn1);
        m0 = mn0; m1 = mn1;
        uint32_t pa[8][2];
        float ps0 = 0.f, ps1 = 0.f;
#pragma unroll
        for (int j = 0; j < 8; ++j) {
            float p00 = __expf(sv[j][0] - m0), p01 = __expf(sv[j][1] - m0);
            float p10 = __expf(sv[j][2] - m1), p11 = __expf(sv[j][3] - m1);
            ps0 += p00 + p01; ps1 += p10 + p11;
            __half2 q0 = __floats2half2_rn(p00, p01);
            __half2 q1 = __floats2half2_rn(p10, p11);
            pa[j][0] = *(uint32_t*)&q0;
            pa[j][1] = *(uint32_t*)&q1;
        }
        l0 = l0 * a0 + ps0; l1 = l1 * a1 + ps1;
#pragma unroll
        for (int j = 0; j < 16; ++j) {
            o[j][0] *= a0; o[j][1] *= a0; o[j][2] *= a1; o[j][3] *= a1;
        }

#pragma unroll
        for (int kk = 0; kk < 4; ++kk) {
            uint32_t afr2[4] = {pa[2 * kk][0], pa[2 * kk][1],
                                pa[2 * kk + 1][0], pa[2 * kk + 1][1]};
#pragma unroll
            for (int j2 = 0; j2 < 8; ++j2) {
                uint32_t bfr[4];
                ldm_x4t(vsm + (kk * 16 + vbRow) * APITCH + j2 * 32 + vbCol, bfr);
                mma16816h(o[2 * j2],     afr2, bfr);
                mma16816h(o[2 * j2 + 1], afr2, bfr + 2);
            }
        }
        __syncthreads();
    }

    l0 += __shfl_xor_sync(0xffffffffu, l0, 1);
    l0 += __shfl_xor_sync(0xffffffffu, l0, 2);
    l1 += __shfl_xor_sync(0xffffffffu, l1, 1);
    l1 += __shfl_xor_sync(0xffffffffu, l1, 2);
    const float i0 = 1.f / l0, i1 = 1.f / l1;
    const int qr0 = s0 + w * 16 + (lane >> 2);
    const size_t base0 = (size_t)(qr0 * BATCH + b) * EMB + h * HD;
    const size_t base1 = (size_t)((qr0 + 8) * BATCH + b) * EMB + h * HD;
#pragma unroll
    for (int j = 0; j < 16; ++j) {
        const int d = j * 8 + ((lane & 3) << 1);
        store2_hl(oh, ol, base0 + d, o[j][0] * i0, o[j][1] * i0);
        store2_hl(oh, ol, base1 + d, o[j][2] * i1, o[j][3] * i1);
    }
}

// ============================================================
extern "C" void kernel_launch(void* const* d_in, const int* in_sizes, int n_in,
                              void* d_out, int out_size) {
    (void)in_sizes; (void)n_in; (void)out_size;
    const float* x      = (const float*)d_in[0];
    const float* w_qkv  = (const float*)d_in[1];
    const float* w_proj = (const float*)d_in[2];
    float* out = (float*)d_out;

    __half *xh, *xl, *wq, *wp, *oh, *ol, *qhp, *khp, *vhp;
    cudaGetSymbolAddress((void**)&xh,  g_xh);
    cudaGetSymbolAddress((void**)&xl,  g_xl);
    cudaGetSymbolAddress((void**)&wq,  g_wq);
    cudaGetSymbolAddress((void**)&wp,  g_wp);
    cudaGetSymbolAddress((void**)&oh,  g_oh);
    cudaGetSymbolAddress((void**)&ol,  g_ol);
    cudaGetSymbolAddress((void**)&qhp, g_qh);
    cudaGetSymbolAddress((void**)&khp, g_kh);
    cudaGetSymbolAddress((void**)&vhp, g_vh);

    cudaFuncSetAttribute(gemm2c,
                         cudaFuncAttributeMaxDynamicSharedMemorySize, GEMM_SMEM);
    cudaFuncSetAttribute(attn_fp16,
                         cudaFuncAttributeMaxDynamicSharedMemorySize, ATTN_SMEM);

    // 0) prologue: x -> hi/lo fp16; weights -> fp16
    {
        int n4;
        n4 = M_TOT * HIDDEN / 4;
        split_half<<<n4 / 256, 256>>>(x, xh, xl, n4);
        n4 = TP * HIDDEN / 4;
        conv_half<<<n4 / 256, 256>>>(w_qkv, wq, n4);
        n4 = HIDDEN * EMB / 4;
        conv_half<<<n4 / 256, 256>>>(w_proj, wp, n4);
    }

    // 1) QKV projection -> fp16 q/k/v (q pre-scaled), fused scatter epilogue
    gemm2c<<<dim3(TP / 128, M_TOT / 128), 256, GEMM_SMEM>>>(
        xh, xl, wq, nullptr, TP, HIDDEN, 1, qhp, khp, vhp);

    // 2) fp16 flash attention (writes hi/lo fp16 split of O)
    attn_fp16<<<dim3(SEQ / 128, NH, BATCH), 256, ATTN_SMEM>>>(
        qhp, khp, vhp, oh, ol);

    // 3) output projection: out[4096,2048] = (Oh+Ol) @ w_proj^T
    gemm2c<<<dim3(EMB / 128, M_TOT / 128), 256, GEMM_SMEM>>>(
        oh, ol, wp, out, EMB, HIDDEN, 0, nullptr, nullptr, nullptr);
}